// round 16
// baseline (speedup 1.0000x reference)
#include <cuda_runtime.h>
#include <cuda_bf16.h>
#include <math.h>
#include <stdint.h>

#define N_NODES 20000
#define N_EDGES 100000
#define N_RELS  1000
#define F_DIM   128
#define N_HEAD  4
#define HC      512            // N_HEAD * F_DIM
#define ETOT    (N_EDGES + N_NODES)
#define NEG_SLOPE 0.2f
#define KTOT    384            // 3-term split contraction length

// ===================== scratch (device globals; allocation-free) ==========
__device__ __align__(16) float    g_xl[(size_t)N_NODES * HC];      // 41 MB
__device__ __align__(16) float    g_xr[(size_t)N_NODES * HC];      // 41 MB
__device__ __align__(16) float    g_RE[(N_RELS + 1) * HC];         // 2 MB
__device__ __align__(16) float    g_relext[(N_RELS + 1) * F_DIM];  // 0.5 MB
__device__ int g_counts[N_RELS];
// CSR (dst-sorted edges, built once per launch)
__device__ int  g_offs[N_NODES + 1];
__device__ int  g_cursor[N_NODES];
__device__ int2 g_epk[ETOT];                                        // (src, rel)
// bf16 3-term split operands: A3[m][384] = [Ah|Al|Ah], W3[l][n][384] = [Wh|Wh|Wl]
__device__ __align__(16) __nv_bfloat16 g_A3[(size_t)N_NODES * KTOT];    // 15.4 MB
__device__ __align__(16) __nv_bfloat16 g_W3[(size_t)4 * 1024 * KTOT];   // 3.1 MB
__device__ __align__(16) float         g_bc[4 * 1024];                  // combined bias

// ===================== generic helpers ====================================
__device__ __forceinline__ float wred(float v) {
    v += __shfl_xor_sync(0xffffffffu, v, 16);
    v += __shfl_xor_sync(0xffffffffu, v, 8);
    v += __shfl_xor_sync(0xffffffffu, v, 4);
    v += __shfl_xor_sync(0xffffffffu, v, 2);
    v += __shfl_xor_sync(0xffffffffu, v, 1);
    return v;
}
__device__ __forceinline__ uint32_t smem_u32(const void* p) {
    uint32_t a;
    asm("{ .reg .u64 t; cvta.to.shared.u64 t, %1; cvt.u32.u64 %0, t; }" : "=r"(a) : "l"(p));
    return a;
}
__device__ __forceinline__ uint32_t swz(uint32_t b) { return b ^ ((b >> 3) & 0x70u); }

// ===================== small utility kernels ==============================
__global__ void fill_u32(unsigned* p, unsigned v, int n) {
    int i = blockIdx.x * blockDim.x + threadIdx.x;
    if (i < n) p[i] = v;
}
__global__ void count_rels(const int* __restrict__ rel, int* __restrict__ counts) {
    int i = blockIdx.x * blockDim.x + threadIdx.x;
    if (i < N_EDGES) atomicAdd(&counts[rel[i]], 1);
}
__global__ void build_relext(const float* __restrict__ relations,
                             const int* __restrict__ counts,
                             float* __restrict__ relext) {
    int r = blockIdx.x;
    int k = threadIdx.x;   // 128
    if (r < N_RELS) {
        relext[r * F_DIM + k] = relations[r * F_DIM + k];
    } else {
        __shared__ int sc[N_RELS];
        for (int i = k; i < N_RELS; i += 128) sc[i] = counts[i];
        __syncthreads();
        float s = 0.f;
        for (int i = 0; i < N_RELS; i++)
            s = fmaf((float)sc[i], relations[i * F_DIM + k], s);
        relext[r * F_DIM + k] = s * (1.0f / (float)N_EDGES);
    }
}

// ---------------- CSR build ----------------
__global__ void count_deg(const int* __restrict__ ei, int* __restrict__ cnt) {
    int e = blockIdx.x * blockDim.x + threadIdx.x;
    if (e < N_EDGES) atomicAdd(&cnt[ei[N_EDGES + e]], 1);
}
__global__ __launch_bounds__(1024) void scan_offsets(const int* __restrict__ cnt,
                                                     int* __restrict__ offs,
                                                     int* __restrict__ cur) {
    __shared__ int part[1024];
    int t = threadIdx.x;
    int base = t * 20;
    int local[20];
    int s = 0;
#pragma unroll
    for (int i = 0; i < 20; i++) {
        int idx = base + i;
        local[i] = s;
        s += (idx < N_NODES) ? cnt[idx] : 0;
    }
    part[t] = s;
    __syncthreads();
    for (int off = 1; off < 1024; off <<= 1) {
        int v = 0;
        if (t >= off) v = part[t - off];
        __syncthreads();
        if (t >= off) part[t] += v;
        __syncthreads();
    }
    int pre = (t > 0) ? part[t - 1] : 0;
#pragma unroll
    for (int i = 0; i < 20; i++) {
        int idx = base + i;
        if (idx < N_NODES) { offs[idx] = pre + local[i]; cur[idx] = pre + local[i]; }
    }
    if (t == 1023) offs[N_NODES] = part[1023];
}
__global__ void scatter_edges(const int* __restrict__ ei, const int* __restrict__ rel,
                              int* __restrict__ cur, int2* __restrict__ epk) {
    int e = blockIdx.x * blockDim.x + threadIdx.x;
    if (e < N_EDGES) {
        int d = ei[N_EDGES + e];
        int pos = atomicAdd(&cur[d], 1);
        epk[pos] = make_int2(ei[e], rel[e]);
    } else if (e < ETOT) {
        int n = e - N_EDGES;
        int pos = atomicAdd(&cur[n], 1);
        epk[pos] = make_int2(n, N_RELS);
    }
}

// A3[m][0:128]=hi, [128:256]=lo, [256:384]=hi  (layer-0 input only)
__global__ void split_A3(const float* __restrict__ in, __nv_bfloat16* __restrict__ A3) {
    int i = blockIdx.x * blockDim.x + threadIdx.x;
    if (i >= N_NODES * F_DIM) return;
    int m = i >> 7, k = i & 127;
    float v = in[i];
    __nv_bfloat16 h = __float2bfloat16(v);
    __nv_bfloat16 l = __float2bfloat16(v - __bfloat162float(h));
    __nv_bfloat16* row = A3 + (size_t)m * KTOT;
    row[k] = h; row[128 + k] = l; row[256 + k] = h;
}

// W3[l][n][0:128]=Wh, [128:256]=Wh, [256:384]=Wl ; n<512 from Wl-proj, else Wr-proj
__global__ void split_W3(const float* __restrict__ Wl, const float* __restrict__ Wr,
                         const float* __restrict__ bl, const float* __restrict__ br,
                         __nv_bfloat16* __restrict__ W3, float* __restrict__ bc) {
    int idx = blockIdx.x * blockDim.x + threadIdx.x;
    if (idx < 4 * 1024) {
        int l = idx >> 10, n = idx & 1023;
        bc[idx] = (n < 512) ? bl[l * 512 + n] : br[l * 512 + (n - 512)];
    }
    if (idx >= 4 * 1024 * F_DIM) return;
    int l = idx / (1024 * F_DIM);
    int rem = idx - l * 1024 * F_DIM;
    int n = rem >> 7, k = rem & 127;
    float v = (n < 512) ? Wl[(size_t)l * F_DIM * 512 + (size_t)k * 512 + n]
                        : Wr[(size_t)l * F_DIM * 512 + (size_t)k * 512 + (n - 512)];
    __nv_bfloat16 h = __float2bfloat16(v);
    __nv_bfloat16 lo = __float2bfloat16(v - __bfloat162float(h));
    __nv_bfloat16* row = W3 + ((size_t)l * 1024 + n) * KTOT;
    row[k] = h; row[128 + k] = h; row[256 + k] = lo;
}

// ===================== mma.sync bf16 GEMM (unchanged, passing) ============
#define BM 128
#define BN 128
#define BK 64
#define NCHUNK 6
#define CHUNK_BYTES 16384
#define BUF_BYTES   32768
#define SMEM_MMA    65536

__device__ __forceinline__ void ldsm4(uint32_t& r0, uint32_t& r1, uint32_t& r2,
                                      uint32_t& r3, uint32_t addr) {
    asm volatile("ldmatrix.sync.aligned.m8n8.x4.shared.b16 {%0,%1,%2,%3}, [%4];"
                 : "=r"(r0), "=r"(r1), "=r"(r2), "=r"(r3) : "r"(addr));
}
__device__ __forceinline__ void mma16816(float* c, const uint32_t* a, const uint32_t* b) {
    asm volatile(
        "mma.sync.aligned.m16n8k16.row.col.f32.bf16.bf16.f32 "
        "{%0,%1,%2,%3}, {%4,%5,%6,%7}, {%8,%9}, {%0,%1,%2,%3};"
        : "+f"(c[0]), "+f"(c[1]), "+f"(c[2]), "+f"(c[3])
        : "r"(a[0]), "r"(a[1]), "r"(a[2]), "r"(a[3]), "r"(b[0]), "r"(b[1]));
}

__global__ __launch_bounds__(256, 2) void gemm_mma(
    const __nv_bfloat16* __restrict__ A3, const __nv_bfloat16* __restrict__ W3,
    const float* __restrict__ bc,
    float* __restrict__ xl, float* __restrict__ xr, int Mtot) {
    extern __shared__ char smem[];
    uint32_t sb = smem_u32(smem);
    int tid = threadIdx.x;
    int wid = tid >> 5, lane = tid & 31;
    int bm = blockIdx.x * BM;
    int n0 = blockIdx.y * BN;
    int wm = wid & 1;
    int wn = wid >> 1;

    auto load_chunk = [&](int buf, int k0) {
        uint32_t abase = sb + buf * BUF_BYTES;
        uint32_t bbase = abase + CHUNK_BYTES;
#pragma unroll
        for (int p = 0; p < 4; p++) {
            int unit = tid + p * 256;
            int row = unit >> 3, c16 = unit & 7;
            uint32_t off = swz((uint32_t)(row * 128 + c16 * 16));
            const void* asrc = A3 + (size_t)(bm + row) * KTOT + k0 + c16 * 8;
            int sz = (bm + row < Mtot) ? 16 : 0;
            asm volatile("cp.async.cg.shared.global [%0], [%1], 16, %2;"
                         :: "r"(abase + off), "l"(asrc), "r"(sz) : "memory");
            const void* bsrc = W3 + (size_t)(n0 + row) * KTOT + k0 + c16 * 8;
            asm volatile("cp.async.cg.shared.global [%0], [%1], 16;"
                         :: "r"(bbase + off), "l"(bsrc) : "memory");
        }
        asm volatile("cp.async.commit_group;" ::: "memory");
    };

    uint32_t aSw[4], bSw[2];
#pragma unroll
    for (int mf = 0; mf < 4; mf++) {
        int row = wm * 64 + mf * 16 + (lane & 15);
        aSw[mf] = swz((uint32_t)(row * 128 + ((lane >> 4) << 4)));
    }
#pragma unroll
    for (int nh = 0; nh < 2; nh++) {
        int row = wn * 32 + nh * 16 + (lane & 7) + ((lane & 16) ? 8 : 0);
        bSw[nh] = swz((uint32_t)(row * 128 + ((lane & 8) ? 16 : 0)));
    }

    float acc[4][4][4] = {};

    load_chunk(0, 0);
#pragma unroll
    for (int c = 0; c < NCHUNK; c++) {
        if (c + 1 < NCHUNK) {
            load_chunk((c + 1) & 1, (c + 1) * BK);
            asm volatile("cp.async.wait_group 1;" ::: "memory");
        } else {
            asm volatile("cp.async.wait_group 0;" ::: "memory");
        }
        __syncthreads();
        uint32_t As = sb + (c & 1) * BUF_BYTES;
        uint32_t Bs = As + CHUNK_BYTES;
#pragma unroll
        for (int kk = 0; kk < 4; kk++) {
            uint32_t kx = (uint32_t)kk << 5;
            uint32_t a[4][4], b[4][2];
#pragma unroll
            for (int mf = 0; mf < 4; mf++)
                ldsm4(a[mf][0], a[mf][1], a[mf][2], a[mf][3], As + (aSw[mf] ^ kx));
#pragma unroll
            for (int nh = 0; nh < 2; nh++) {
                uint32_t r0, r1, r2, r3;
                ldsm4(r0, r1, r2, r3, Bs + (bSw[nh] ^ kx));
                b[nh * 2][0] = r0; b[nh * 2][1] = r1;
                b[nh * 2 + 1][0] = r2; b[nh * 2 + 1][1] = r3;
            }
#pragma unroll
            for (int mf = 0; mf < 4; mf++)
#pragma unroll
                for (int nf = 0; nf < 4; nf++)
                    mma16816(acc[mf][nf], a[mf], b[nf]);
        }
        __syncthreads();
    }

    float* outp = (n0 < 512) ? xl : xr;
    int col0 = (n0 < 512) ? n0 : n0 - 512;
#pragma unroll
    for (int mf = 0; mf < 4; mf++) {
        int m0 = bm + wm * 64 + mf * 16 + (lane >> 2);
#pragma unroll
        for (int nf = 0; nf < 4; nf++) {
            int cl = wn * 32 + nf * 8 + (lane & 3) * 2;
            float bx = __ldg(bc + n0 + cl), by = __ldg(bc + n0 + cl + 1);
            if (m0 < Mtot) {
                float2 v = make_float2(acc[mf][nf][0] + bx, acc[mf][nf][1] + by);
                *(float2*)(outp + (size_t)m0 * 512 + col0 + cl) = v;
            }
            if (m0 + 8 < Mtot) {
                float2 v = make_float2(acc[mf][nf][2] + bx, acc[mf][nf][3] + by);
                *(float2*)(outp + (size_t)(m0 + 8) * 512 + col0 + cl) = v;
            }
        }
    }
}

// ===================== fp32 GEMM (small RE matmul) ========================
__global__ __launch_bounds__(256) void gemm_k128(const float* __restrict__ A,
                                                 const float* __restrict__ W,
                                                 const float* __restrict__ bias,
                                                 float* __restrict__ C, int M) {
    __shared__ __align__(16) float As[16][64];
    __shared__ __align__(16) float Ws[16][64];
    int tid = threadIdx.x;
    int bm = blockIdx.x * 64;
    int bn = blockIdx.y * 64;
    int tx = tid & 15, ty = tid >> 4;
    float acc[4][4];
#pragma unroll
    for (int i = 0; i < 4; i++)
#pragma unroll
        for (int j = 0; j < 4; j++) acc[i][j] = 0.f;
    int arow = tid >> 2;
    int akq  = (tid & 3) * 4;
    int wkr  = tid >> 4;
    int wnq  = (tid & 15) * 4;
    const bool avalid = (bm + arow) < M;
    const float* aptr = A + (size_t)(bm + arow) * F_DIM + akq;
    const float* wptr = W + (size_t)wkr * HC + bn + wnq;
    for (int k0 = 0; k0 < 128; k0 += 16) {
        float4 av = avalid ? *(const float4*)(aptr + k0) : make_float4(0.f, 0.f, 0.f, 0.f);
        float4 wv = *(const float4*)(wptr + (size_t)k0 * HC);
        As[akq + 0][arow] = av.x; As[akq + 1][arow] = av.y;
        As[akq + 2][arow] = av.z; As[akq + 3][arow] = av.w;
        *(float4*)&Ws[wkr][wnq] = wv;
        __syncthreads();
#pragma unroll
        for (int kk = 0; kk < 16; kk++) {
            float a[4], b[4];
            *(float4*)a = *(const float4*)&As[kk][ty * 4];
            *(float4*)b = *(const float4*)&Ws[kk][tx * 4];
#pragma unroll
            for (int i = 0; i < 4; i++)
#pragma unroll
                for (int j = 0; j < 4; j++)
                    acc[i][j] = fmaf(a[i], b[j], acc[i][j]);
        }
        __syncthreads();
    }
#pragma unroll
    for (int i = 0; i < 4; i++) {
        int row = bm + ty * 4 + i;
        if (row < M) {
            float4 o;
            o.x = acc[i][0]; o.y = acc[i][1]; o.z = acc[i][2]; o.w = acc[i][3];
            *(float4*)(C + (size_t)row * HC + bn + tx * 4) = o;
        }
    }
}

// ===================== fused GAT edge pass ================================
// One warp per dst node, register software-pipelining one edge ahead.
__device__ __forceinline__ float score_head(const float4& xl4, const float4& xr4,
                                            const float4& e4, const float4& at4) {
    float vx = xl4.x + xr4.x + e4.x; vx = vx > 0.f ? vx : NEG_SLOPE * vx;
    float vy = xl4.y + xr4.y + e4.y; vy = vy > 0.f ? vy : NEG_SLOPE * vy;
    float vz = xl4.z + xr4.z + e4.z; vz = vz > 0.f ? vz : NEG_SLOPE * vz;
    float vw = xl4.w + xr4.w + e4.w; vw = vw > 0.f ? vw : NEG_SLOPE * vw;
    return wred(fmaf(vx, at4.x, fmaf(vy, at4.y, fmaf(vz, at4.z, vw * at4.w))));
}
__device__ __forceinline__ void upd_head(float lg, const float4& xl4,
                                         float& m, float& den, float4& acc) {
    float nm = fmaxf(m, lg);
    float sc = __expf(m - nm);
    float p  = __expf(lg - nm);
    den = den * sc + p;
    acc.x = fmaf(acc.x, sc, p * xl4.x);
    acc.y = fmaf(acc.y, sc, p * xl4.y);
    acc.z = fmaf(acc.z, sc, p * xl4.z);
    acc.w = fmaf(acc.w, sc, p * xl4.w);
    m = nm;
}

#define LOADR(PK, X0, X1, X2, X3, E0, E1, E2, E3) do {                      \
    const float4* _pxl = (const float4*)(xl + (size_t)(PK).x * HC);         \
    const float4* _pe  = (const float4*)(RE + (size_t)(PK).y * HC);         \
    X0 = _pxl[lane]; X1 = _pxl[32 + lane]; X2 = _pxl[64 + lane]; X3 = _pxl[96 + lane]; \
    E0 = _pe[lane];  E1 = _pe[32 + lane];  E2 = _pe[64 + lane];  E3 = _pe[96 + lane];  \
} while (0)

#define CONSUME(X0, X1, X2, X3, E0, E1, E2, E3) do {                        \
    float _l0 = score_head(X0, xr0, E0, sat[lane]);                         \
    float _l1 = score_head(X1, xr1, E1, sat[32 + lane]);                    \
    float _l2 = score_head(X2, xr2, E2, sat[64 + lane]);                    \
    float _l3 = score_head(X3, xr3, E3, sat[96 + lane]);                    \
    upd_head(_l0, X0, m0, den0, acc0);                                      \
    upd_head(_l1, X1, m1, den1, acc1);                                      \
    upd_head(_l2, X2, m2, den2, acc2);                                      \
    upd_head(_l3, X3, m3, den3, acc3);                                      \
} while (0)

__global__ __launch_bounds__(128) void gat_fused(
    const float* __restrict__ xl, const float* __restrict__ xr,
    const float* __restrict__ RE,
    const int2* __restrict__ epk, const int* __restrict__ offs,
    const float* __restrict__ att, const float* __restrict__ bias,
    float* __restrict__ out, __nv_bfloat16* __restrict__ a3) {
    __shared__ float4 sat[128];          // att: 4 heads x 32 float4 (block-uniform)
    int t = threadIdx.x;
    sat[t] = ((const float4*)att)[t];
    __syncthreads();

    int node = (blockIdx.x * 128 + t) >> 5;
    int lane = t & 31;
    if (node >= N_NODES) return;
    int beg = offs[node], end = offs[node + 1];

    const float4* pxr = (const float4*)(xr + (size_t)node * HC);
    float4 xr0 = pxr[lane], xr1 = pxr[32 + lane], xr2 = pxr[64 + lane], xr3 = pxr[96 + lane];

    float m0 = -3.0e38f, m1 = -3.0e38f, m2 = -3.0e38f, m3 = -3.0e38f;
    float den0 = 0.f, den1 = 0.f, den2 = 0.f, den3 = 0.f;
    float4 acc0 = {0, 0, 0, 0}, acc1 = {0, 0, 0, 0}, acc2 = {0, 0, 0, 0}, acc3 = {0, 0, 0, 0};

    float4 xa0, xa1, xa2, xa3, ea0, ea1, ea2, ea3;
    float4 xb0, xb1, xb2, xb3, eb0, eb1, eb2, eb3;

    int e = beg;
    int2 pk = epk[e];
    LOADR(pk, xa0, xa1, xa2, xa3, ea0, ea1, ea2, ea3);
    while (true) {
        if (e + 1 < end) { pk = epk[e + 1]; LOADR(pk, xb0, xb1, xb2, xb3, eb0, eb1, eb2, eb3); }
        CONSUME(xa0, xa1, xa2, xa3, ea0, ea1, ea2, ea3);
        e++;
        if (e >= end) break;
        if (e + 1 < end) { pk = epk[e + 1]; LOADR(pk, xa0, xa1, xa2, xa3, ea0, ea1, ea2, ea3); }
        CONSUME(xb0, xb1, xb2, xb3, eb0, eb1, eb2, eb3);
        e++;
        if (e >= end) break;
    }

    float i0 = 0.25f / den0, i1 = 0.25f / den1, i2 = 0.25f / den2, i3 = 0.25f / den3;
    float4 b4 = ((const float4*)bias)[lane];
    float4 o;
    o.x = fmaf(acc0.x, i0, fmaf(acc1.x, i1, fmaf(acc2.x, i2, fmaf(acc3.x, i3, b4.x))));
    o.y = fmaf(acc0.y, i0, fmaf(acc1.y, i1, fmaf(acc2.y, i2, fmaf(acc3.y, i3, b4.y))));
    o.z = fmaf(acc0.z, i0, fmaf(acc1.z, i1, fmaf(acc2.z, i2, fmaf(acc3.z, i3, b4.z))));
    o.w = fmaf(acc0.w, i0, fmaf(acc1.w, i1, fmaf(acc2.w, i2, fmaf(acc3.w, i3, b4.w))));

    if (out) {
        ((float4*)(out + (size_t)node * F_DIM))[lane] = o;
    }
    if (a3) {
        float of[4] = {o.x, o.y, o.z, o.w};
        __nv_bfloat16 h[4], lo[4];
#pragma unroll
        for (int j = 0; j < 4; j++) {
            h[j] = __float2bfloat16(of[j]);
            lo[j] = __float2bfloat16(of[j] - __bfloat162float(h[j]));
        }
        __nv_bfloat16* row = a3 + (size_t)node * KTOT + lane * 4;
        *(__nv_bfloat162*)(row)       = *(__nv_bfloat162*)&h[0];
        *(__nv_bfloat162*)(row + 2)   = *(__nv_bfloat162*)&h[2];
        *(__nv_bfloat162*)(row + 128) = *(__nv_bfloat162*)&lo[0];
        *(__nv_bfloat162*)(row + 130) = *(__nv_bfloat162*)&lo[2];
        *(__nv_bfloat162*)(row + 256) = *(__nv_bfloat162*)&h[0];
        *(__nv_bfloat162*)(row + 258) = *(__nv_bfloat162*)&h[2];
    }
}

// ===================== tail: copy relations into output ===================
__global__ void copy_rel(const float* __restrict__ relations, float* __restrict__ out) {
    int i = blockIdx.x * blockDim.x + threadIdx.x;
    if (i < N_RELS * F_DIM) out[(size_t)N_NODES * F_DIM + i] = relations[i];
}

// ===================== host ===============================================
extern "C" void kernel_launch(void* const* d_in, const int* in_sizes, int n_in,
                              void* d_out, int out_size) {
    (void)in_sizes; (void)n_in; (void)out_size;
    const float* x         = (const float*)d_in[0];
    const int*   ei        = (const int*)  d_in[1];
    const float* relations = (const float*)d_in[2];
    const int*   relidx    = (const int*)  d_in[3];
    const float* Wl        = (const float*)d_in[4];
    const float* bl        = (const float*)d_in[5];
    const float* Wr        = (const float*)d_in[6];
    const float* br        = (const float*)d_in[7];
    const float* We        = (const float*)d_in[8];
    const float* att       = (const float*)d_in[9];
    const float* bias      = (const float*)d_in[10];
    float* out = (float*)d_out;

    float *xl, *xr, *RE, *relext, *bc;
    int *counts, *offs, *cursor;
    int2* epk;
    __nv_bfloat16 *A3, *W3;
    cudaGetSymbolAddress((void**)&xl, g_xl);
    cudaGetSymbolAddress((void**)&xr, g_xr);
    cudaGetSymbolAddress((void**)&RE, g_RE);
    cudaGetSymbolAddress((void**)&relext, g_relext);
    cudaGetSymbolAddress((void**)&counts, g_counts);
    cudaGetSymbolAddress((void**)&offs, g_offs);
    cudaGetSymbolAddress((void**)&cursor, g_cursor);
    cudaGetSymbolAddress((void**)&epk, g_epk);
    cudaGetSymbolAddress((void**)&A3, g_A3);
    cudaGetSymbolAddress((void**)&W3, g_W3);
    cudaGetSymbolAddress((void**)&bc, g_bc);

    cudaFuncSetAttribute(gemm_mma, cudaFuncAttributeMaxDynamicSharedMemorySize, SMEM_MMA);

    // ---- CSR build (once; graph static within launch). counts init = 1 (self loop).
    fill_u32<<<(N_NODES + 255) / 256, 256>>>((unsigned*)cursor, 1u, N_NODES);
    count_deg<<<(N_EDGES + 255) / 256, 256>>>(ei, cursor);
    scan_offsets<<<1, 1024>>>(cursor, offs, cursor);
    scatter_edges<<<(ETOT + 255) / 256, 256>>>(ei, relidx, cursor, epk);

    // ---- relation mean + weight transpose/split
    fill_u32<<<(N_RELS + 255) / 256, 256>>>((unsigned*)counts, 0u, N_RELS);
    count_rels<<<(N_EDGES + 255) / 256, 256>>>(relidx, counts);
    build_relext<<<N_RELS + 1, 128>>>(relations, counts, relext);
    split_W3<<<(4 * 1024 * F_DIM + 255) / 256, 256>>>(Wl, Wr, bl, br, W3, bc);

    // layer-0 operand split from x
    split_A3<<<(N_NODES * F_DIM + 255) / 256, 256>>>(x, A3);

    dim3 gMMA((N_NODES + BM - 1) / BM, 1024 / BN);   // 157 x 8
    dim3 gR((N_RELS + 1 + 63) / 64, HC / 64);
    int nodeBlocks = (N_NODES * 32 + 127) / 128;

    for (int l = 0; l < 4; l++) {
        gemm_mma<<<gMMA, 256, SMEM_MMA>>>(A3, W3 + (size_t)l * 1024 * KTOT,
                                          bc + l * 1024, xl, xr, N_NODES);
        gemm_k128<<<gR, 256>>>(relext, We + (size_t)l * F_DIM * HC, (const float*)0, RE, N_RELS + 1);
        gat_fused<<<nodeBlocks, 128>>>(xl, xr, RE, epk, offs,
                                       att + l * N_HEAD * F_DIM, bias + l * F_DIM,
                                       (l == 3) ? out : (float*)0,
                                       (l < 3) ? A3 : (__nv_bfloat16*)0);
    }
    copy_rel<<<(N_RELS * F_DIM + 255) / 256, 256>>>(relations, out);
}